// round 16
// baseline (speedup 1.0000x reference)
#include <cuda_runtime.h>
#include <cuda_bf16.h>
#include <cstdint>
#include <math.h>

// ---------------------------------------------------------------------------
// TransFuse on GB300 — round 15 = round 9 + warp-decoupled GEMM pipelines:
// each warp owns a private 2-stage smem region and its own cp.async groups;
// NO __syncthreads in the mainloop. Prepass/combines/grids = round 9.
// ---------------------------------------------------------------------------

__device__ __nv_bfloat16 g_wb[154500000];
__device__ __nv_bfloat16 g_act[14336000];
__device__ __nv_bfloat16 g_bridge[4096000];
__device__ __nv_bfloat16 g_fuse[3072000];
__device__ __nv_bfloat16 g_h1[524288];
__device__ __nv_bfloat16 g_h2[131072];
__device__ float g_part[20000000];

#define OFF_SG 0
#define OFF_GP 100000000
#define OFF_BR 115000000
#define OFF_PP 139000000
#define OFF_H1 148000000
#define OFF_H2 154200000

#define STR 20                 // u32 row stride
#define WSTAGE_B 10240         // bytes per warp stage: A 64*20*4 + B 64*20*4
#define WREGION_B 20480        // 2 stages per warp
// total smem = 4 * 20480 = 81920 B

__device__ __forceinline__ uint32_t pack_bf16(float lo, float hi) {
    uint32_t r;
    asm("cvt.rn.bf16x2.f32 %0, %1, %2;" : "=r"(r) : "f"(hi), "f"(lo));
    return r;
}
__device__ __forceinline__ uint32_t smem_u32(const void* p) {
    uint32_t a;
    asm("{ .reg .u64 t; cvta.to.shared.u64 t, %1; cvt.u32.u64 %0, t; }" : "=r"(a) : "l"(p));
    return a;
}
__device__ __forceinline__ void cp16(uint32_t dst, const void* src, bool p) {
    int sz = p ? 16 : 0;
    asm volatile("cp.async.cg.shared.global [%0], [%1], 16, %2;\n" :: "r"(dst), "l"(src), "r"(sz));
}
__device__ __forceinline__ void cp_commit() { asm volatile("cp.async.commit_group;\n"); }
template <int N_> __device__ __forceinline__ void cp_wait() {
    asm volatile("cp.async.wait_group %0;\n" :: "n"(N_));
}
__device__ __forceinline__ void ldsm4(uint32_t* r, uint32_t addr) {
    asm volatile("ldmatrix.sync.aligned.m8n8.x4.shared.b16 {%0,%1,%2,%3}, [%4];"
                 : "=r"(r[0]), "=r"(r[1]), "=r"(r[2]), "=r"(r[3]) : "r"(addr));
}
__device__ __forceinline__ void mma_bf16(float c[4], const uint32_t a[4], const uint32_t b[2]) {
    asm volatile(
        "mma.sync.aligned.m16n8k16.row.col.f32.bf16.bf16.f32 "
        "{%0,%1,%2,%3}, {%4,%5,%6,%7}, {%8,%9}, {%0,%1,%2,%3};\n"
        : "+f"(c[0]), "+f"(c[1]), "+f"(c[2]), "+f"(c[3])
        : "r"(a[0]), "r"(a[1]), "r"(a[2]), "r"(a[3]), "r"(b[0]), "r"(b[1]));
}

// ---------------- prepass (measured 85% DRAM, unchanged) ----------------
__global__ __launch_bounds__(256)
void mask_pack(const float* __restrict__ W, const float* __restrict__ adj,
               __nv_bfloat16* __restrict__ out, int N, int K)
{
    __shared__ float adjs[32][132];
    const int k0 = blockIdx.x * 32;
    const int n0 = blockIdx.y * 128;
    const int t = threadIdx.x;
    #pragma unroll
    for (int i = 0; i < 4; ++i) {
        int idx = t + i * 256;
        int kk = idx >> 5;
        int nc = (idx & 31) * 4;
        bool p = (k0 + kk) < K && (n0 + nc) < N;
        float4 v = make_float4(0.f, 0.f, 0.f, 0.f);
        if (p) v = *reinterpret_cast<const float4*>(adj + (size_t)(k0 + kk) * N + n0 + nc);
        *reinterpret_cast<float4*>(&adjs[kk][nc]) = v;
    }
    __syncthreads();
    #pragma unroll
    for (int i = 0; i < 2; ++i) {
        int idx = t + i * 256;
        int n  = idx >> 2;
        int kc = idx & 3;
        int gn = n0 + n;
        int gk = k0 + kc * 8;
        if (gn >= N || gk >= K) continue;
        const float* wp = W + (size_t)gn * K + gk;
        float4 w0 = *reinterpret_cast<const float4*>(wp);
        float4 w1 = *reinterpret_cast<const float4*>(wp + 4);
        uint4 o;
        o.x = pack_bf16(w0.x * adjs[kc*8+0][n], w0.y * adjs[kc*8+1][n]);
        o.y = pack_bf16(w0.z * adjs[kc*8+2][n], w0.w * adjs[kc*8+3][n]);
        o.z = pack_bf16(w1.x * adjs[kc*8+4][n], w1.y * adjs[kc*8+5][n]);
        o.w = pack_bf16(w1.z * adjs[kc*8+6][n], w1.w * adjs[kc*8+7][n]);
        *reinterpret_cast<uint4*>(out + (size_t)gn * K + gk) = o;
    }
}

__global__ void conv_bf16(const float* __restrict__ src, __nv_bfloat16* __restrict__ dst, int n4)
{
    int i = blockIdx.x * 256 + threadIdx.x;
    if (i >= n4) return;
    float4 v = *reinterpret_cast<const float4*>(src + (size_t)i * 4);
    uint2 o;
    o.x = pack_bf16(v.x, v.y);
    o.y = pack_bf16(v.z, v.w);
    *reinterpret_cast<uint2*>(dst + (size_t)i * 4) = o;
}

// ------------- warp-decoupled GEMM: BM=BN=128, BK=32, 128 threads -------------
struct LayerP {
    const __nv_bfloat16* A;
    const __nv_bfloat16* W;
    const float* bias;   // null -> fp32 partial at out + s*512*N
    void* out;
    int ldA, ldOut, N, K, KT, nt, kpc, base;
};
struct FusedParams { int nlayers; LayerP L[3]; };

__global__ __launch_bounds__(128, 2)
void fused_gemm(FusedParams P)
{
    extern __shared__ uint32_t sm[];   // 4 warps * WREGION_B

    const int bid = blockIdx.x;
    int li = 0;
    #pragma unroll
    for (int i = 1; i < 3; ++i)
        if (i < P.nlayers && bid >= P.L[i].base) li = i;
    const LayerP L = P.L[li];

    const int local = bid - L.base;
    const int per_split = L.nt * 4;
    const int s   = local / per_split;
    const int rr  = local % per_split;
    const int n_t = rr >> 2;
    const int m_t = rr & 3;
    const int m0 = m_t * 128;
    const int n0 = n_t * 128;
    const int kt0 = s * L.kpc;
    const int kt1 = min(L.KT, kt0 + L.kpc);
    const int nk = kt1 - kt0;

    const int t    = threadIdx.x;
    const int warp = t >> 5;
    const int lane = t & 31;
    const int wm = (warp >> 1) * 64;
    const int wn = (warp & 1) * 64;

    float acc[4][8][4];
    #pragma unroll
    for (int mt = 0; mt < 4; ++mt)
        #pragma unroll
        for (int nt = 0; nt < 8; ++nt)
            #pragma unroll
            for (int i = 0; i < 4; ++i) acc[mt][nt][i] = 0.0f;

    // per-lane staging pointers: lane owns A rows (wm + r4 + 8j), chunk c4
    const int r4 = lane >> 2;          // 0..7
    const int c4 = lane & 3;           // 16B chunk within 64B row
    const __nv_bfloat16* aptr = L.A + (size_t)(m0 + wm + r4) * L.ldA + c4 * 8;
    const int bRow0 = n0 + wn + r4;    // B rows bRow0 + 8j
    const int bClamp = bRow0 < L.N ? bRow0 : (L.N - 1);
    const __nv_bfloat16* wptr = L.W + (size_t)bClamp * L.K + c4 * 8;

    const uint32_t wbase = smem_u32(sm) + (uint32_t)warp * WREGION_B;
    const uint32_t adst0 = wbase + (uint32_t)(r4 * STR + c4 * 4) * 4;
    const uint32_t bdst0 = adst0 + 5120;

    // ldmatrix lane addressing within the warp's 64-row tiles
    const int lrA = (lane & 7) | (((lane >> 3) & 1) << 3);
    const int lcA = (lane >> 4) * 4;
    const uint32_t aln = (uint32_t)(lrA * STR + lcA) * 4;
    const int lrB = (lane & 7) | (((lane >> 4) & 1) << 3);
    const int lcB = ((lane >> 3) & 1) * 4;
    const uint32_t bln = (uint32_t)(lrB * STR + lcB) * 4 + 5120;

    auto issue = [&](int i) {
        const int k0 = (kt0 + i) * 32;
        const uint32_t so = (uint32_t)(i & 1) * WSTAGE_B;
        const bool pk = k0 < L.K;      // full 32-chunk valid iff k0 < K (K % 8 == 0; kpc aligned)
        #pragma unroll
        for (int j = 0; j < 8; ++j)
            cp16(adst0 + so + (uint32_t)j * (8 * STR * 4),
                 aptr + (size_t)j * 8 * L.ldA + k0, pk);
        #pragma unroll
        for (int j = 0; j < 8; ++j) {
            bool pb = pk && (bRow0 + 8 * j) < L.N;
            cp16(bdst0 + so + (uint32_t)j * (8 * STR * 4),
                 wptr + (size_t)j * 8 * L.K + k0, pb);
        }
        cp_commit();
    };

    // per-warp 2-deep prologue
    issue(0);
    if (nk > 1) issue(1); else cp_commit();

    for (int i = 0; i < nk; ++i) {
        if (i + 1 < nk) cp_wait<1>(); else cp_wait<0>();

        const uint32_t sb = wbase + (uint32_t)(i & 1) * WSTAGE_B;
        const uint32_t aB = sb + aln;
        const uint32_t bB = sb + bln;

        #pragma unroll
        for (int ks = 0; ks < 2; ++ks) {
            uint32_t af[4][4];
            #pragma unroll
            for (int mt = 0; mt < 4; ++mt)
                ldsm4(af[mt], aB + (uint32_t)(mt * 16 * STR + ks * 8) * 4);
            uint32_t bv[4][4];
            #pragma unroll
            for (int p = 0; p < 4; ++p)
                ldsm4(bv[p], bB + (uint32_t)(p * 16 * STR + ks * 8) * 4);
            #pragma unroll
            for (int p = 0; p < 4; ++p) {
                uint32_t b0[2] = { bv[p][0], bv[p][1] };
                uint32_t b1[2] = { bv[p][2], bv[p][3] };
                #pragma unroll
                for (int mt = 0; mt < 4; ++mt) {
                    mma_bf16(acc[mt][2 * p],     af[mt], b0);
                    mma_bf16(acc[mt][2 * p + 1], af[mt], b1);
                }
            }
        }
        // refill the buffer just consumed (in-order: all LDSMs above already executed)
        if (i + 2 < nk) issue(i + 2); else cp_commit();
    }

    const bool fin = (L.bias != nullptr);
    #pragma unroll
    for (int mt = 0; mt < 4; ++mt) {
        #pragma unroll
        for (int nt = 0; nt < 8; ++nt) {
            const int m = m0 + wm + mt * 16 + (lane >> 2);
            const int n = n0 + wn + nt * 8 + (lane & 3) * 2;
            if (n >= L.N) continue;
            float* cr = acc[mt][nt];
            if (fin) {
                float b0 = L.bias[n], b1 = L.bias[n + 1];
                float v00 = cr[0] + b0, v01 = cr[1] + b1;
                float v10 = cr[2] + b0, v11 = cr[3] + b1;
                v00 = v00 > 0.f ? v00 : 0.f;  v01 = v01 > 0.f ? v01 : 0.f;
                v10 = v10 > 0.f ? v10 : 0.f;  v11 = v11 > 0.f ? v11 : 0.f;
                __nv_bfloat16* ob = (__nv_bfloat16*)L.out;
                *reinterpret_cast<uint32_t*>(ob + (size_t)m * L.ldOut + n) = pack_bf16(v00, v01);
                *reinterpret_cast<uint32_t*>(ob + (size_t)(m + 8) * L.ldOut + n) = pack_bf16(v10, v11);
            } else {
                float* op = (float*)L.out + (size_t)s * 512 * L.N;
                op[(size_t)m * L.N + n]           = cr[0];
                op[(size_t)m * L.N + n + 1]       = cr[1];
                op[(size_t)(m + 8) * L.N + n]     = cr[2];
                op[(size_t)(m + 8) * L.N + n + 1] = cr[3];
            }
        }
    }
}

template <int S>
__global__ void combine_k(const float* __restrict__ part, int N,
                          const float* __restrict__ bias,
                          __nv_bfloat16* __restrict__ out, int ldOut)
{
    int i = blockIdx.x * 256 + threadIdx.x;
    int half = 512 * (N >> 1);
    if (i >= half) return;
    int m = i / (N >> 1);
    int n = (i - m * (N >> 1)) * 2;
    size_t o = (size_t)m * N + n;
    float v0 = 0.f, v1 = 0.f;
    #pragma unroll
    for (int s = 0; s < S; ++s) {
        v0 += part[(size_t)s * 512 * N + o];
        v1 += part[(size_t)s * 512 * N + o + 1];
    }
    v0 += bias[n];     v1 += bias[n + 1];
    v0 = v0 > 0.f ? v0 : 0.f;
    v1 = v1 > 0.f ? v1 : 0.f;
    *reinterpret_cast<uint32_t*>(out + (size_t)m * ldOut + n) = pack_bf16(v0, v1);
}

__global__ void head_kernel(const __nv_bfloat16* __restrict__ h2,
                            const float* __restrict__ W_out,
                            const float* __restrict__ b_out,
                            float* __restrict__ out)
{
    int b = blockIdx.x;
    int lane = threadIdx.x;
    float s = 0.f;
    #pragma unroll
    for (int k = lane; k < 256; k += 32)
        s += __bfloat162float(h2[b * 256 + k]) * W_out[k];
    #pragma unroll
    for (int o = 16; o > 0; o >>= 1)
        s += __shfl_down_sync(0xFFFFFFFFu, s, o);
    if (lane == 0)
        out[b] = 1.0f / (1.0f + expf(-(s + b_out[0])));
}

static constexpr int GEMM_SMEM = 4 * WREGION_B;   // 81920

extern "C" void kernel_launch(void* const* d_in, const int* in_sizes, int n_in,
                              void* d_out, int out_size)
{
    const float* in_mat  = (const float*)d_in[0];
    const float* adj_sg  = (const float*)d_in[1];
    const float* adj_gp  = (const float*)d_in[2];
    const float* adj_br  = (const float*)d_in[3];
    const float* adj_pp  = (const float*)d_in[4];
    const float* W_sg    = (const float*)d_in[5];
    const float* b_sg    = (const float*)d_in[6];
    const float* W_gp    = (const float*)d_in[7];
    const float* b_gp    = (const float*)d_in[8];
    const float* W_br    = (const float*)d_in[9];
    const float* b_br    = (const float*)d_in[10];
    const float* W_pp    = (const float*)d_in[11];
    const float* b_pp    = (const float*)d_in[12];
    const float* W_h1    = (const float*)d_in[13];
    const float* b_h1    = (const float*)d_in[14];
    const float* W_h2    = (const float*)d_in[15];
    const float* b_h2    = (const float*)d_in[16];
    const float* W_out   = (const float*)d_in[17];
    const float* b_out   = (const float*)d_in[18];
    float* out = (float*)d_out;

    cudaFuncSetAttribute(fused_gemm, cudaFuncAttributeMaxDynamicSharedMemorySize, GEMM_SMEM);

    __nv_bfloat16 *wb, *act, *bridge, *fuse, *h1, *h2;
    float* part;
    cudaGetSymbolAddress((void**)&wb,     g_wb);
    cudaGetSymbolAddress((void**)&act,    g_act);
    cudaGetSymbolAddress((void**)&bridge, g_bridge);
    cudaGetSymbolAddress((void**)&fuse,   g_fuse);
    cudaGetSymbolAddress((void**)&h1,     g_h1);
    cudaGetSymbolAddress((void**)&h2,     g_h2);
    cudaGetSymbolAddress((void**)&part,   g_part);

    // phase 0: prepass
    conv_bf16<<<(14336000 / 4 + 255) / 256, 256>>>(in_mat, act, 14336000 / 4);
    conv_bf16<<<(6144000 / 4 + 255) / 256, 256>>>(W_h1, wb + OFF_H1, 6144000 / 4);
    conv_bf16<<<(262144 / 4 + 255) / 256, 256>>>(W_h2, wb + OFF_H2, 262144 / 4);
    mask_pack<<<dim3(625, 40), 256>>>(W_sg, adj_sg, wb + OFF_SG, 5000, 20000);
    mask_pack<<<dim3(157, 24), 256>>>(W_gp, adj_gp, wb + OFF_GP, 3000, 5000);
    mask_pack<<<dim3(250, 24), 256>>>(W_br, adj_br, wb + OFF_BR, 3000, 8000);
    mask_pack<<<dim3(94, 24),  256>>>(W_pp, adj_pp, wb + OFF_PP, 3000, 3000);

    const size_t PART_GP = 15360000;   // after sg's 6*512*5000

    // phase 1: snp(S=6) + gene(S=2) + protein(final) = 1248 CTAs
    {
        FusedParams P; P.nlayers = 3;
        P.L[0] = { act + 8000, wb + OFF_SG, nullptr, part,
                   28000, 5000, 5000, 20000, 625, 40, 105, 0 };
        P.L[1] = { act + 3000, wb + OFF_GP, nullptr, part + PART_GP,
                   28000, 3000, 3000, 5000, 157, 24, 79, 960 };
        P.L[2] = { act, wb + OFF_PP, b_pp, fuse + 3000,
                   28000, 6000, 3000, 3000, 94, 24, 94, 1152 };
        fused_gemm<<<1248, 128, GEMM_SMEM>>>(P);
    }
    combine_k<6><<<(512 * 2500 + 255) / 256, 256>>>(part, 5000, b_sg, bridge, 8000);
    combine_k<2><<<(512 * 1500 + 255) / 256, 256>>>(part + PART_GP, 3000, b_gp, bridge + 5000, 8000);

    // phase 2: bridge (S=3)
    {
        FusedParams P; P.nlayers = 1;
        P.L[0] = { bridge, wb + OFF_BR, nullptr, part,
                   8000, 3000, 3000, 8000, 250, 24, 84, 0 };
        fused_gemm<<<288, 128, GEMM_SMEM>>>(P);
    }
    combine_k<3><<<(512 * 1500 + 255) / 256, 256>>>(part, 3000, b_br, fuse, 6000);

    // phase 3: h1 (S=8)
    {
        FusedParams P; P.nlayers = 1;
        P.L[0] = { fuse, wb + OFF_H1, nullptr, part,
                   6000, 1024, 1024, 6000, 188, 8, 24, 0 };
        fused_gemm<<<256, 128, GEMM_SMEM>>>(P);
    }
    combine_k<8><<<(512 * 512 + 255) / 256, 256>>>(part, 1024, b_h1, h1, 1024);

    // phase 4: h2 (final) + head
    {
        FusedParams P; P.nlayers = 1;
        P.L[0] = { h1, wb + OFF_H2, b_h2, h2,
                   1024, 256, 256, 1024, 32, 2, 32, 0 };
        fused_gemm<<<8, 128, GEMM_SMEM>>>(P);
    }
    head_kernel<<<512, 32>>>(h2, W_out, b_out, out);
}

// round 17
// speedup vs baseline: 1.0224x; 1.0224x over previous
#include <cuda_runtime.h>
#include <cuda_bf16.h>
#include <cstdint>
#include <math.h>

// ---------------------------------------------------------------------------
// TransFuse on GB300 — round 17 = round-15 warp-decoupled GEMM (WIN) with
// (a) per-chunk K predicate fix (round 15 read past row end when K % 32 != 0),
// (b) tail-packed phase-1 grid (gene S=4 -> 1440 CTAs = 4.86 waves).
// ---------------------------------------------------------------------------

__device__ __nv_bfloat16 g_wb[154500000];
__device__ __nv_bfloat16 g_act[14336000];
__device__ __nv_bfloat16 g_bridge[4096000];
__device__ __nv_bfloat16 g_fuse[3072000];
__device__ __nv_bfloat16 g_h1[524288];
__device__ __nv_bfloat16 g_h2[131072];
__device__ float g_part[21600000];

#define OFF_SG 0
#define OFF_GP 100000000
#define OFF_BR 115000000
#define OFF_PP 139000000
#define OFF_H1 148000000
#define OFF_H2 154200000

#define STR 20                 // u32 row stride
#define WSTAGE_B 10240         // bytes per warp stage: A 64*20*4 + B 64*20*4
#define WREGION_B 20480        // 2 stages per warp; total 4*20480 = 81920 B

__device__ __forceinline__ uint32_t pack_bf16(float lo, float hi) {
    uint32_t r;
    asm("cvt.rn.bf16x2.f32 %0, %1, %2;" : "=r"(r) : "f"(hi), "f"(lo));
    return r;
}
__device__ __forceinline__ uint32_t smem_u32(const void* p) {
    uint32_t a;
    asm("{ .reg .u64 t; cvta.to.shared.u64 t, %1; cvt.u32.u64 %0, t; }" : "=r"(a) : "l"(p));
    return a;
}
__device__ __forceinline__ void cp16(uint32_t dst, const void* src, bool p) {
    int sz = p ? 16 : 0;
    asm volatile("cp.async.cg.shared.global [%0], [%1], 16, %2;\n" :: "r"(dst), "l"(src), "r"(sz));
}
__device__ __forceinline__ void cp_commit() { asm volatile("cp.async.commit_group;\n"); }
template <int N_> __device__ __forceinline__ void cp_wait() {
    asm volatile("cp.async.wait_group %0;\n" :: "n"(N_));
}
__device__ __forceinline__ void ldsm4(uint32_t* r, uint32_t addr) {
    asm volatile("ldmatrix.sync.aligned.m8n8.x4.shared.b16 {%0,%1,%2,%3}, [%4];"
                 : "=r"(r[0]), "=r"(r[1]), "=r"(r[2]), "=r"(r[3]) : "r"(addr));
}
__device__ __forceinline__ void mma_bf16(float c[4], const uint32_t a[4], const uint32_t b[2]) {
    asm volatile(
        "mma.sync.aligned.m16n8k16.row.col.f32.bf16.bf16.f32 "
        "{%0,%1,%2,%3}, {%4,%5,%6,%7}, {%8,%9}, {%0,%1,%2,%3};\n"
        : "+f"(c[0]), "+f"(c[1]), "+f"(c[2]), "+f"(c[3])
        : "r"(a[0]), "r"(a[1]), "r"(a[2]), "r"(a[3]), "r"(b[0]), "r"(b[1]));
}

// ---------------- prepass (measured 85% DRAM, unchanged) ----------------
__global__ __launch_bounds__(256)
void mask_pack(const float* __restrict__ W, const float* __restrict__ adj,
               __nv_bfloat16* __restrict__ out, int N, int K)
{
    __shared__ float adjs[32][132];
    const int k0 = blockIdx.x * 32;
    const int n0 = blockIdx.y * 128;
    const int t = threadIdx.x;
    #pragma unroll
    for (int i = 0; i < 4; ++i) {
        int idx = t + i * 256;
        int kk = idx >> 5;
        int nc = (idx & 31) * 4;
        bool p = (k0 + kk) < K && (n0 + nc) < N;
        float4 v = make_float4(0.f, 0.f, 0.f, 0.f);
        if (p) v = *reinterpret_cast<const float4*>(adj + (size_t)(k0 + kk) * N + n0 + nc);
        *reinterpret_cast<float4*>(&adjs[kk][nc]) = v;
    }
    __syncthreads();
    #pragma unroll
    for (int i = 0; i < 2; ++i) {
        int idx = t + i * 256;
        int n  = idx >> 2;
        int kc = idx & 3;
        int gn = n0 + n;
        int gk = k0 + kc * 8;
        if (gn >= N || gk >= K) continue;
        const float* wp = W + (size_t)gn * K + gk;
        float4 w0 = *reinterpret_cast<const float4*>(wp);
        float4 w1 = *reinterpret_cast<const float4*>(wp + 4);
        uint4 o;
        o.x = pack_bf16(w0.x * adjs[kc*8+0][n], w0.y * adjs[kc*8+1][n]);
        o.y = pack_bf16(w0.z * adjs[kc*8+2][n], w0.w * adjs[kc*8+3][n]);
        o.z = pack_bf16(w1.x * adjs[kc*8+4][n], w1.y * adjs[kc*8+5][n]);
        o.w = pack_bf16(w1.z * adjs[kc*8+6][n], w1.w * adjs[kc*8+7][n]);
        *reinterpret_cast<uint4*>(out + (size_t)gn * K + gk) = o;
    }
}

__global__ void conv_bf16(const float* __restrict__ src, __nv_bfloat16* __restrict__ dst, int n4)
{
    int i = blockIdx.x * 256 + threadIdx.x;
    if (i >= n4) return;
    float4 v = *reinterpret_cast<const float4*>(src + (size_t)i * 4);
    uint2 o;
    o.x = pack_bf16(v.x, v.y);
    o.y = pack_bf16(v.z, v.w);
    *reinterpret_cast<uint2*>(dst + (size_t)i * 4) = o;
}

// ------------- warp-decoupled GEMM: BM=BN=128, BK=32, 128 threads -------------
struct LayerP {
    const __nv_bfloat16* A;
    const __nv_bfloat16* W;
    const float* bias;   // null -> fp32 partial at out + s*512*N
    void* out;
    int ldA, ldOut, N, K, KT, nt, kpc, base;
};
struct FusedParams { int nlayers; LayerP L[3]; };

__global__ __launch_bounds__(128, 2)
void fused_gemm(FusedParams P)
{
    extern __shared__ uint32_t sm[];   // 4 warps * WREGION_B

    const int bid = blockIdx.x;
    int li = 0;
    #pragma unroll
    for (int i = 1; i < 3; ++i)
        if (i < P.nlayers && bid >= P.L[i].base) li = i;
    const LayerP L = P.L[li];

    const int local = bid - L.base;
    const int per_split = L.nt * 4;
    const int s   = local / per_split;
    const int rr  = local % per_split;
    const int n_t = rr >> 2;
    const int m_t = rr & 3;
    const int m0 = m_t * 128;
    const int n0 = n_t * 128;
    const int kt0 = s * L.kpc;
    const int kt1 = min(L.KT, kt0 + L.kpc);
    const int nk = kt1 - kt0;

    const int t    = threadIdx.x;
    const int warp = t >> 5;
    const int lane = t & 31;
    const int wm = (warp >> 1) * 64;
    const int wn = (warp & 1) * 64;

    float acc[4][8][4];
    #pragma unroll
    for (int mt = 0; mt < 4; ++mt)
        #pragma unroll
        for (int nt = 0; nt < 8; ++nt)
            #pragma unroll
            for (int i = 0; i < 4; ++i) acc[mt][nt][i] = 0.0f;

    // per-lane staging pointers: lane owns A rows (wm + r4 + 8j), chunk c4
    const int r4 = lane >> 2;          // 0..7
    const int c4 = lane & 3;           // 16B chunk within 64B row
    const __nv_bfloat16* aptr = L.A + (size_t)(m0 + wm + r4) * L.ldA + c4 * 8;
    const int bRow0 = n0 + wn + r4;    // B rows bRow0 + 8j
    const int bClamp = bRow0 < L.N ? bRow0 : (L.N - 1);
    const __nv_bfloat16* wptr = L.W + (size_t)bClamp * L.K + c4 * 8;

    const uint32_t wbase = smem_u32(sm) + (uint32_t)warp * WREGION_B;
    const uint32_t adst0 = wbase + (uint32_t)(r4 * STR + c4 * 4) * 4;
    const uint32_t bdst0 = adst0 + 5120;

    // ldmatrix lane addressing within the warp's 64-row tiles
    const int lrA = (lane & 7) | (((lane >> 3) & 1) << 3);
    const int lcA = (lane >> 4) * 4;
    const uint32_t aln = (uint32_t)(lrA * STR + lcA) * 4;
    const int lrB = (lane & 7) | (((lane >> 4) & 1) << 3);
    const int lcB = ((lane >> 3) & 1) * 4;
    const uint32_t bln = (uint32_t)(lrB * STR + lcB) * 4 + 5120;

    auto issue = [&](int i) {
        const int k0 = (kt0 + i) * 32;
        const uint32_t so = (uint32_t)(i & 1) * WSTAGE_B;
        // per-lane chunk predicate: this lane's 8-bf16 chunk starts at k0+c4*8
        // (all layer K are multiples of 8 -> chunk fully valid or fully invalid)
        const bool pk = (k0 + c4 * 8) < L.K;
        #pragma unroll
        for (int j = 0; j < 8; ++j)
            cp16(adst0 + so + (uint32_t)j * (8 * STR * 4),
                 aptr + (size_t)j * 8 * L.ldA + k0, pk);
        #pragma unroll
        for (int j = 0; j < 8; ++j) {
            bool pb = pk && (bRow0 + 8 * j) < L.N;
            cp16(bdst0 + so + (uint32_t)j * (8 * STR * 4),
                 wptr + (size_t)j * 8 * L.K + k0, pb);
        }
        cp_commit();
    };

    // per-warp 2-deep prologue
    issue(0);
    if (nk > 1) issue(1); else cp_commit();

    for (int i = 0; i < nk; ++i) {
        if (i + 1 < nk) cp_wait<1>(); else cp_wait<0>();

        const uint32_t sb = wbase + (uint32_t)(i & 1) * WSTAGE_B;
        const uint32_t aB = sb + aln;
        const uint32_t bB = sb + bln;

        #pragma unroll
        for (int ks = 0; ks < 2; ++ks) {
            uint32_t af[4][4];
            #pragma unroll
            for (int mt = 0; mt < 4; ++mt)
                ldsm4(af[mt], aB + (uint32_t)(mt * 16 * STR + ks * 8) * 4);
            uint32_t bv[4][4];
            #pragma unroll
            for (int p = 0; p < 4; ++p)
                ldsm4(bv[p], bB + (uint32_t)(p * 16 * STR + ks * 8) * 4);
            #pragma unroll
            for (int p = 0; p < 4; ++p) {
                uint32_t b0[2] = { bv[p][0], bv[p][1] };
                uint32_t b1[2] = { bv[p][2], bv[p][3] };
                #pragma unroll
                for (int mt = 0; mt < 4; ++mt) {
                    mma_bf16(acc[mt][2 * p],     af[mt], b0);
                    mma_bf16(acc[mt][2 * p + 1], af[mt], b1);
                }
            }
        }
        // refill the buffer just consumed (in-order: all LDSMs above already executed)
        if (i + 2 < nk) issue(i + 2); else cp_commit();
    }

    const bool fin = (L.bias != nullptr);
    #pragma unroll
    for (int mt = 0; mt < 4; ++mt) {
        #pragma unroll
        for (int nt = 0; nt < 8; ++nt) {
            const int m = m0 + wm + mt * 16 + (lane >> 2);
            const int n = n0 + wn + nt * 8 + (lane & 3) * 2;
            if (n >= L.N) continue;
            float* cr = acc[mt][nt];
            if (fin) {
                float b0 = L.bias[n], b1 = L.bias[n + 1];
                float v00 = cr[0] + b0, v01 = cr[1] + b1;
                float v10 = cr[2] + b0, v11 = cr[3] + b1;
                v00 = v00 > 0.f ? v00 : 0.f;  v01 = v01 > 0.f ? v01 : 0.f;
                v10 = v10 > 0.f ? v10 : 0.f;  v11 = v11 > 0.f ? v11 : 0.f;
                __nv_bfloat16* ob = (__nv_bfloat16*)L.out;
                *reinterpret_cast<uint32_t*>(ob + (size_t)m * L.ldOut + n) = pack_bf16(v00, v01);
                *reinterpret_cast<uint32_t*>(ob + (size_t)(m + 8) * L.ldOut + n) = pack_bf16(v10, v11);
            } else {
                float* op = (float*)L.out + (size_t)s * 512 * L.N;
                op[(size_t)m * L.N + n]           = cr[0];
                op[(size_t)m * L.N + n + 1]       = cr[1];
                op[(size_t)(m + 8) * L.N + n]     = cr[2];
                op[(size_t)(m + 8) * L.N + n + 1] = cr[3];
            }
        }
    }
}

template <int S>
__global__ void combine_k(const float* __restrict__ part, int N,
                          const float* __restrict__ bias,
                          __nv_bfloat16* __restrict__ out, int ldOut)
{
    int i = blockIdx.x * 256 + threadIdx.x;
    int half = 512 * (N >> 1);
    if (i >= half) return;
    int m = i / (N >> 1);
    int n = (i - m * (N >> 1)) * 2;
    size_t o = (size_t)m * N + n;
    float v0 = 0.f, v1 = 0.f;
    #pragma unroll
    for (int s = 0; s < S; ++s) {
        v0 += part[(size_t)s * 512 * N + o];
        v1 += part[(size_t)s * 512 * N + o + 1];
    }
    v0 += bias[n];     v1 += bias[n + 1];
    v0 = v0 > 0.f ? v0 : 0.f;
    v1 = v1 > 0.f ? v1 : 0.f;
    *reinterpret_cast<uint32_t*>(out + (size_t)m * ldOut + n) = pack_bf16(v0, v1);
}

__global__ void head_kernel(const __nv_bfloat16* __restrict__ h2,
                            const float* __restrict__ W_out,
                            const float* __restrict__ b_out,
                            float* __restrict__ out)
{
    int b = blockIdx.x;
    int lane = threadIdx.x;
    float s = 0.f;
    #pragma unroll
    for (int k = lane; k < 256; k += 32)
        s += __bfloat162float(h2[b * 256 + k]) * W_out[k];
    #pragma unroll
    for (int o = 16; o > 0; o >>= 1)
        s += __shfl_down_sync(0xFFFFFFFFu, s, o);
    if (lane == 0)
        out[b] = 1.0f / (1.0f + expf(-(s + b_out[0])));
}

static constexpr int GEMM_SMEM = 4 * WREGION_B;   // 81920

extern "C" void kernel_launch(void* const* d_in, const int* in_sizes, int n_in,
                              void* d_out, int out_size)
{
    const float* in_mat  = (const float*)d_in[0];
    const float* adj_sg  = (const float*)d_in[1];
    const float* adj_gp  = (const float*)d_in[2];
    const float* adj_br  = (const float*)d_in[3];
    const float* adj_pp  = (const float*)d_in[4];
    const float* W_sg    = (const float*)d_in[5];
    const float* b_sg    = (const float*)d_in[6];
    const float* W_gp    = (const float*)d_in[7];
    const float* b_gp    = (const float*)d_in[8];
    const float* W_br    = (const float*)d_in[9];
    const float* b_br    = (const float*)d_in[10];
    const float* W_pp    = (const float*)d_in[11];
    const float* b_pp    = (const float*)d_in[12];
    const float* W_h1    = (const float*)d_in[13];
    const float* b_h1    = (const float*)d_in[14];
    const float* W_h2    = (const float*)d_in[15];
    const float* b_h2    = (const float*)d_in[16];
    const float* W_out   = (const float*)d_in[17];
    const float* b_out   = (const float*)d_in[18];
    float* out = (float*)d_out;

    cudaFuncSetAttribute(fused_gemm, cudaFuncAttributeMaxDynamicSharedMemorySize, GEMM_SMEM);

    __nv_bfloat16 *wb, *act, *bridge, *fuse, *h1, *h2;
    float* part;
    cudaGetSymbolAddress((void**)&wb,     g_wb);
    cudaGetSymbolAddress((void**)&act,    g_act);
    cudaGetSymbolAddress((void**)&bridge, g_bridge);
    cudaGetSymbolAddress((void**)&fuse,   g_fuse);
    cudaGetSymbolAddress((void**)&h1,     g_h1);
    cudaGetSymbolAddress((void**)&h2,     g_h2);
    cudaGetSymbolAddress((void**)&part,   g_part);

    // phase 0: prepass
    conv_bf16<<<(14336000 / 4 + 255) / 256, 256>>>(in_mat, act, 14336000 / 4);
    conv_bf16<<<(6144000 / 4 + 255) / 256, 256>>>(W_h1, wb + OFF_H1, 6144000 / 4);
    conv_bf16<<<(262144 / 4 + 255) / 256, 256>>>(W_h2, wb + OFF_H2, 262144 / 4);
    mask_pack<<<dim3(625, 40), 256>>>(W_sg, adj_sg, wb + OFF_SG, 5000, 20000);
    mask_pack<<<dim3(157, 24), 256>>>(W_gp, adj_gp, wb + OFF_GP, 3000, 5000);
    mask_pack<<<dim3(250, 24), 256>>>(W_br, adj_br, wb + OFF_BR, 3000, 8000);
    mask_pack<<<dim3(94, 24),  256>>>(W_pp, adj_pp, wb + OFF_PP, 3000, 3000);

    const size_t PART_GP = 15360000;   // after sg's 6*512*5000

    // phase 1: snp(S=6, 960) + gene(S=4, 384) + protein(final, 96) = 1440 CTAs
    {
        FusedParams P; P.nlayers = 3;
        P.L[0] = { act + 8000, wb + OFF_SG, nullptr, part,
                   28000, 5000, 5000, 20000, 625, 40, 105, 0 };
        P.L[1] = { act + 3000, wb + OFF_GP, nullptr, part + PART_GP,
                   28000, 3000, 3000, 5000, 157, 24, 40, 960 };
        P.L[2] = { act, wb + OFF_PP, b_pp, fuse + 3000,
                   28000, 6000, 3000, 3000, 94, 24, 94, 1344 };
        fused_gemm<<<1440, 128, GEMM_SMEM>>>(P);
    }
    combine_k<6><<<(512 * 2500 + 255) / 256, 256>>>(part, 5000, b_sg, bridge, 8000);
    combine_k<4><<<(512 * 1500 + 255) / 256, 256>>>(part + PART_GP, 3000, b_gp, bridge + 5000, 8000);

    // phase 2: bridge (S=3)
    {
        FusedParams P; P.nlayers = 1;
        P.L[0] = { bridge, wb + OFF_BR, nullptr, part,
                   8000, 3000, 3000, 8000, 250, 24, 84, 0 };
        fused_gemm<<<288, 128, GEMM_SMEM>>>(P);
    }
    combine_k<3><<<(512 * 1500 + 255) / 256, 256>>>(part, 3000, b_br, fuse, 6000);

    // phase 3: h1 (S=8)
    {
        FusedParams P; P.nlayers = 1;
        P.L[0] = { fuse, wb + OFF_H1, nullptr, part,
                   6000, 1024, 1024, 6000, 188, 8, 24, 0 };
        fused_gemm<<<256, 128, GEMM_SMEM>>>(P);
    }
    combine_k<8><<<(512 * 512 + 255) / 256, 256>>>(part, 1024, b_h1, h1, 1024);

    // phase 4: h2 (final) + head
    {
        FusedParams P; P.nlayers = 1;
        P.L[0] = { h1, wb + OFF_H2, b_h2, h2,
                   1024, 256, 256, 1024, 32, 2, 32, 0 };
        fused_gemm<<<8, 128, GEMM_SMEM>>>(P);
    }
    head_kernel<<<512, 32>>>(h2, W_out, b_out, out);
}